// round 12
// baseline (speedup 1.0000x reference)
#include <cuda_runtime.h>
#include <cstdint>

#define N_PAIRS 64000
#define N_ATOMS 16000
#define NF 8
#define NH 100
#define KDIM 900            // (NF+1)*NH
#define MAX_DEG 48

#define BMP 56              // atom-PAIRS per CTA (112 rows) -> grid 143, single wave
#define GRID ((N_ATOMS / 2 + BMP - 1) / BMP)    // 143
#define BK 36               // K chunk; 25 stages
#define NITER 25
#define THREADS 256         // 8 warps; warp w owns pairs [7w,7w+7), lane l cols [4l,4l+4)
#define PPW 7               // pairs per warp

#define SPAIR_B 288                  // BK * 8 bytes per pair per stage
#define SS_STAGE (BMP * SPAIR_B)     // 16128 B
#define WS_STAGE (BK * 1024)         // 36864 B (128 dup'd cols * 8B per k)
#define SMEM_TOTAL (2 * (SS_STAGE + WS_STAGE))   // 105984 B

// ---------------------------------------------------------------------------
// Scratch (static device globals; no runtime allocation allowed)
// ---------------------------------------------------------------------------
__device__ float    g_S2[(size_t)(N_ATOMS / 2) * KDIM * 2]; // [pair][k][2] 57.6MB
__device__ float    g_Wt2[(size_t)KDIM * 256];              // [k][n] dup (w,w), 128 cols
__device__ uint32_t g_cursor[N_ATOMS];
__device__ uint32_t g_elist[(size_t)N_ATOMS * MAX_DEG];

__device__ __forceinline__ uint32_t smem_u32(const void* p) {
    uint32_t a;
    asm("{ .reg .u64 t; cvta.to.shared.u64 t, %1; cvt.u32.u64 %0, t; }" : "=r"(a) : "l"(p));
    return a;
}

// ---------------------------------------------------------------------------
// prep: g_Wt2[k][n] = (v,v); k=f*100+j; f<8 -> W[f, n*100+j]; f==8 -> b; pad 0.
// ---------------------------------------------------------------------------
__global__ void prep_wt_kernel(const float* __restrict__ W, const float* __restrict__ b) {
    int tid = blockIdx.x * blockDim.x + threadIdx.x;
    if (tid >= KDIM * 32) return;
    int k = tid >> 5;
    int q = tid & 31;          // 4-col group
    int f = k / NH;
    int j = k - f * NH;
    float v[4];
#pragma unroll
    for (int i = 0; i < 4; i++) {
        int n = q * 4 + i;
        v[i] = 0.f;
        if (n < NH)
            v[i] = (f < NF) ? W[f * (NH * NH) + n * NH + j] : b[n * NH + j];
    }
    float* dst = g_Wt2 + (size_t)k * 256 + q * 8;
    *(float4*)(dst + 0) = make_float4(v[0], v[0], v[1], v[1]);
    *(float4*)(dst + 4) = make_float4(v[2], v[2], v[3], v[3]);
}

// ---------------------------------------------------------------------------
// Bucket fill: elist[dst][pos] = e  (cursor pre-zeroed)
// ---------------------------------------------------------------------------
__global__ void fill_kernel(const int* __restrict__ a2p) {
    int e = blockIdx.x * blockDim.x + threadIdx.x;
    if (e >= N_PAIRS) return;
    int dst = a2p[2 * e];
    uint32_t pos = atomicAdd(&g_cursor[dst], 1u);
    if (pos < MAX_DEG) g_elist[(size_t)dst * MAX_DEG + pos] = (uint32_t)e;
}

// ---------------------------------------------------------------------------
// Gather (pair version): thread = (pair p, q in [0,25)). Accumulates both
// atoms 2p, 2p+1 over their incident edges; writes interleaved [k][2] layout.
// ---------------------------------------------------------------------------
__global__ void gather_kernel(const float* __restrict__ pf,
                              const float* __restrict__ af,
                              const int*   __restrict__ a2p) {
    int tid = threadIdx.x;                 // 0..249 (10 pairs per block)
    if (tid >= 250) return;
    int p = blockIdx.x * 10 + tid / 25;
    int q = tid % 25;

    float acc0[9][4], acc1[9][4];
#pragma unroll
    for (int f = 0; f < 9; f++)
#pragma unroll
        for (int i = 0; i < 4; i++) { acc0[f][i] = 0.f; acc1[f][i] = 0.f; }

#pragma unroll
    for (int half = 0; half < 2; half++) {
        int a = 2 * p + half;
        int deg = (int)g_cursor[a];
        if (deg > MAX_DEG) deg = MAX_DEG;
        const uint32_t* lst = g_elist + (size_t)a * MAX_DEG;
        float (*acc)[4] = half ? acc1 : acc0;
        for (int i = 0; i < deg; i++) {
            int e = (int)lst[i];
            int src = a2p[2 * e + 1];
            float4 v  = *(const float4*)(af + (size_t)src * NH + q * 4);
            float4 c0 = *(const float4*)(pf + (size_t)e * NF);
            float4 c1 = *(const float4*)(pf + (size_t)e * NF + 4);
            float coef[9] = {c0.x, c0.y, c0.z, c0.w, c1.x, c1.y, c1.z, c1.w, 1.0f};
#pragma unroll
            for (int f = 0; f < 9; f++) {
                acc[f][0] += coef[f] * v.x;
                acc[f][1] += coef[f] * v.y;
                acc[f][2] += coef[f] * v.z;
                acc[f][3] += coef[f] * v.w;
            }
        }
    }

    // element (k, atomHalf) at p*1800 + k*2 + half;  k = f*100 + q*4 + i
    float* base = g_S2 + (size_t)p * (KDIM * 2) + q * 8;
#pragma unroll
    for (int f = 0; f < 9; f++) {
        *(float4*)(base + f * 200 + 0) =
            make_float4(acc0[f][0], acc1[f][0], acc0[f][1], acc1[f][1]);
        *(float4*)(base + f * 200 + 4) =
            make_float4(acc0[f][2], acc1[f][2], acc0[f][3], acc1[f][3]);
    }
}

// ---------------------------------------------------------------------------
// GEMM: out[16000,100] = S[16000,900] @ Wt[900,128]
// 8 warps x 7 atom-pairs; lane = 4 cols. S = broadcast v2.u64 of pair-
// interleaved values; W = pre-duplicated (w,w). Inner loop: loads + FFMA2 only.
// ---------------------------------------------------------------------------
__global__ void __launch_bounds__(THREADS, 1) gemm_kernel(float* __restrict__ out) {
    extern __shared__ char smem[];
    uint32_t ss = smem_u32(smem);
    uint32_t ws = ss + 2 * SS_STAGE;

    int tid = threadIdx.x;
    int w   = tid >> 5;          // warp -> pairs [7w, 7w+7)
    int l   = tid & 31;          // lane -> cols [4l, 4l+4)
    int p0  = blockIdx.x * BMP;  // first global pair of this CTA

    unsigned long long acc[PPW][4];
#pragma unroll
    for (int pr = 0; pr < PPW; pr++)
#pragma unroll
        for (int c = 0; c < 4; c++) acc[pr][c] = 0ULL;

    // Stage loads: S = 56 pairs * 18 chunks = 1008; W = 2304 chunks (16B each).
    auto issue_stage = [&](int stage, int c) {
        uint32_t sdst = ss + stage * SS_STAGE;
        uint32_t wdst = ws + stage * WS_STAGE;
        const char* wsrc = (const char*)g_Wt2 + (size_t)c * WS_STAGE;
#pragma unroll
        for (int i = 0; i < 4; i++) {
            int t = tid + i * THREADS;
            if (t < BMP * 18) {
                int pr = t / 18, idx = t - pr * 18;
                int gp = p0 + pr;
                if (gp >= N_ATOMS / 2) gp = N_ATOMS / 2 - 1;   // clamp
                asm volatile("cp.async.ca.shared.global [%0], [%1], 16;"
                             :: "r"(sdst + pr * SPAIR_B + idx * 16),
                                "l"((const char*)(g_S2 + (size_t)gp * (KDIM * 2)) +
                                    c * SPAIR_B + idx * 16)
                             : "memory");
            }
        }
#pragma unroll
        for (int i = 0; i < 9; i++) {
            int t = tid + i * THREADS;
            asm volatile("cp.async.ca.shared.global [%0], [%1], 16;"
                         :: "r"(wdst + t * 16), "l"(wsrc + t * 16) : "memory");
        }
        asm volatile("cp.async.commit_group;" ::: "memory");
    };

    issue_stage(0, 0);
    asm volatile("cp.async.wait_group 0;" ::: "memory");
    __syncthreads();

    for (int c = 0; c < NITER; ++c) {
        int cur = c & 1;
        bool more = (c + 1 < NITER);
        if (more) issue_stage(cur ^ 1, c + 1);

        uint32_t sa = ss + cur * SS_STAGE + (w * PPW) * SPAIR_B;
        uint32_t wa = ws + cur * WS_STAGE + l * 32;

#pragma unroll
        for (int kq = 0; kq < BK / 2; kq++) {   // 2 k's per step
            // S: per pair, 16B broadcast = (k0 pair, k1 pair)
            unsigned long long sv[PPW][2];
#pragma unroll
            for (int pr = 0; pr < PPW; pr++)
                asm("ld.shared.v2.u64 {%0,%1}, [%2];"
                    : "=l"(sv[pr][0]), "=l"(sv[pr][1])
                    : "r"(sa + pr * SPAIR_B + kq * 16));
            // W: per k, lane's 4 dup'd cols = 32B
            unsigned long long wv[2][4];
#pragma unroll
            for (int kk = 0; kk < 2; kk++) {
                uint32_t a = wa + (kq * 2 + kk) * 1024;
                asm("ld.shared.v2.u64 {%0,%1}, [%2];"
                    : "=l"(wv[kk][0]), "=l"(wv[kk][1]) : "r"(a));
                asm("ld.shared.v2.u64 {%0,%1}, [%2];"
                    : "=l"(wv[kk][2]), "=l"(wv[kk][3]) : "r"(a + 16));
            }
#pragma unroll
            for (int pr = 0; pr < PPW; pr++)
#pragma unroll
                for (int kk = 0; kk < 2; kk++)
#pragma unroll
                    for (int cc = 0; cc < 4; cc++)
                        asm volatile("fma.rn.f32x2 %0, %1, %2, %0;"
                                     : "+l"(acc[pr][cc])
                                     : "l"(sv[pr][kk]), "l"(wv[kk][cc]));
        }

        if (more) asm volatile("cp.async.wait_group 0;" ::: "memory");
        __syncthreads();
    }

    // epilogue: pair -> rows (2gp, 2gp+1); cols 4l..4l+3 (l<25)
    if (l < 25) {
#pragma unroll
        for (int pr = 0; pr < PPW; pr++) {
            int gp = p0 + w * PPW + pr;
            if (2 * gp < N_ATOMS) {
                float e0, o0, e1, o1, e2, o2, e3, o3;
                asm("mov.b64 {%0,%1}, %2;" : "=f"(e0), "=f"(o0) : "l"(acc[pr][0]));
                asm("mov.b64 {%0,%1}, %2;" : "=f"(e1), "=f"(o1) : "l"(acc[pr][1]));
                asm("mov.b64 {%0,%1}, %2;" : "=f"(e2), "=f"(o2) : "l"(acc[pr][2]));
                asm("mov.b64 {%0,%1}, %2;" : "=f"(e3), "=f"(o3) : "l"(acc[pr][3]));
                *(float4*)(out + (size_t)(2 * gp) * NH + l * 4) =
                    make_float4(e0, e1, e2, e3);
                *(float4*)(out + (size_t)(2 * gp + 1) * NH + l * 4) =
                    make_float4(o0, o1, o2, o3);
            }
        }
    }
}

// ---------------------------------------------------------------------------
extern "C" void kernel_launch(void* const* d_in, const int* in_sizes, int n_in,
                              void* d_out, int out_size) {
    const float* pf  = (const float*)d_in[0];   // [64000, 8]
    const float* af  = (const float*)d_in[1];   // [16000, 100]
    const int*   a2p = (const int*)  d_in[2];   // [64000, 2]
    const float* W   = (const float*)d_in[3];   // [8, 10000]
    const float* b   = (const float*)d_in[4];   // [10000]
    float* out = (float*)d_out;                 // [16000, 100]

    void* cur_ptr = nullptr;
    cudaGetSymbolAddress(&cur_ptr, g_cursor);
    cudaFuncSetAttribute(gemm_kernel,
                         cudaFuncAttributeMaxDynamicSharedMemorySize, SMEM_TOTAL);

    prep_wt_kernel<<<(KDIM * 32 + 255) / 256, 256>>>(W, b);
    cudaMemsetAsync(cur_ptr, 0, N_ATOMS * sizeof(uint32_t));
    fill_kernel<<<(N_PAIRS + 255) / 256, 256>>>(a2p);
    gather_kernel<<<(N_ATOMS / 2) / 10, 250>>>(pf, af, a2p);
    gemm_kernel<<<GRID, THREADS, SMEM_TOTAL>>>(out);
}

// round 15
// speedup vs baseline: 1.1569x; 1.1569x over previous
#include <cuda_runtime.h>
#include <cstdint>

#define N_PAIRS 64000
#define N_ATOMS 16000
#define NF 8
#define NH 100
#define KDIM 900            // (NF+1)*NH
#define NPAD 128            // padded cols (100 real + 28 zero)
#define BM 112              // rows per CTA -> 143 CTAs, single wave on 148 SMs
#define GRID ((N_ATOMS + BM - 1) / BM)   // 143
#define BK 36               // K chunk; 25 iters
#define NITER 25
#define THREADS 448         // 14 warps; warp w rows [8w,8w+8), lane l cols [4l,4l+4)
#define RPW 8               // rows per warp
#define MAX_DEG 48          // bucket capacity (Poisson(4): P(d>=48) ~ 0)
#define NSTAGE 3

#define SROW_B 144          // 36 floats * 4 B per S tile row
#define SS_STAGE (BM * SROW_B)       // 16128 B
#define WS_STAGE (BK * NPAD * 4)     // 18432 B
#define SMEM_TOTAL (NSTAGE * (SS_STAGE + WS_STAGE))   // 103680 B

// ---------------------------------------------------------------------------
// Scratch (static device globals; no runtime allocation allowed)
// ---------------------------------------------------------------------------
__device__ float    g_S[(size_t)N_ATOMS * KDIM];       // 57.6 MB, [atom][900]
__device__ float    g_Wt[(size_t)KDIM * NPAD];         // Wt[k][n], padded cols
__device__ uint32_t g_cursor[N_ATOMS];                 // per-atom degree
__device__ uint32_t g_elist[(size_t)N_ATOMS * MAX_DEG];// edge id buckets

__device__ __forceinline__ uint32_t smem_u32(const void* p) {
    uint32_t a;
    asm("{ .reg .u64 t; cvta.to.shared.u64 t, %1; cvt.u32.u64 %0, t; }" : "=r"(a) : "l"(p));
    return a;
}

// ---------------------------------------------------------------------------
// prep (float4): g_Wt[k*128+n]; k=f*100+j; f<8 -> W[f, n*100+j]; f==8 -> b
// ---------------------------------------------------------------------------
__global__ void prep_wt_kernel(const float* __restrict__ W, const float* __restrict__ b) {
    int tid = blockIdx.x * blockDim.x + threadIdx.x;
    if (tid >= KDIM * (NPAD / 4)) return;
    int k = tid >> 5;
    int q = tid & 31;
    int f = k / NH;
    int j = k - f * NH;
    float v[4];
#pragma unroll
    for (int i = 0; i < 4; i++) {
        int n = q * 4 + i;
        v[i] = 0.f;
        if (n < NH)
            v[i] = (f < NF) ? W[f * (NH * NH) + n * NH + j] : b[n * NH + j];
    }
    *(float4*)(g_Wt + (size_t)k * NPAD + q * 4) = make_float4(v[0], v[1], v[2], v[3]);
}

// ---------------------------------------------------------------------------
// Bucket fill: elist[dst][pos] = e  (cursor pre-zeroed)
// ---------------------------------------------------------------------------
__global__ void fill_kernel(const int* __restrict__ a2p) {
    int e = blockIdx.x * blockDim.x + threadIdx.x;
    if (e >= N_PAIRS) return;
    int dst = a2p[2 * e];
    uint32_t pos = atomicAdd(&g_cursor[dst], 1u);
    if (pos < MAX_DEG) g_elist[(size_t)dst * MAX_DEG + pos] = (uint32_t)e;
}

// ---------------------------------------------------------------------------
// Gather: thread = (atom a, q in [0,25)). Accumulates S[a, f*100+q*4..+3]
// for all 9 features over a's incident edges; one STG.128 per feature.
// ---------------------------------------------------------------------------
__global__ void gather_kernel(const float* __restrict__ pf,
                              const float* __restrict__ af,
                              const int*   __restrict__ a2p) {
    int tid = threadIdx.x;                 // 0..249 (10 atoms per block)
    if (tid >= 250) return;
    int a = blockIdx.x * 10 + tid / 25;
    int q = tid % 25;

    int deg = (int)g_cursor[a];
    if (deg > MAX_DEG) deg = MAX_DEG;

    float acc[9][4];
#pragma unroll
    for (int f = 0; f < 9; f++)
#pragma unroll
        for (int i = 0; i < 4; i++) acc[f][i] = 0.f;

    const uint32_t* lst = g_elist + (size_t)a * MAX_DEG;
    for (int i = 0; i < deg; i++) {
        int e = (int)lst[i];
        int src = a2p[2 * e + 1];
        float4 v  = *(const float4*)(af + (size_t)src * NH + q * 4);
        float4 c0 = *(const float4*)(pf + (size_t)e * NF);
        float4 c1 = *(const float4*)(pf + (size_t)e * NF + 4);
        float coef[9] = {c0.x, c0.y, c0.z, c0.w, c1.x, c1.y, c1.z, c1.w, 1.0f};
#pragma unroll
        for (int f = 0; f < 9; f++) {
            acc[f][0] += coef[f] * v.x;
            acc[f][1] += coef[f] * v.y;
            acc[f][2] += coef[f] * v.z;
            acc[f][3] += coef[f] * v.w;
        }
    }

    float* base = g_S + (size_t)a * KDIM + q * 4;
#pragma unroll
    for (int f = 0; f < 9; f++)
        *(float4*)(base + f * NH) = make_float4(acc[f][0], acc[f][1], acc[f][2], acc[f][3]);
}

// ---------------------------------------------------------------------------
// GEMM: out[16000,100] = S[16000,900] @ Wt[900,128]
// 14 warps x 8 rows; lane = 4 cols. S reads warp-broadcast v4; W reads
// 16B/lane. Packed f32x2 FMA accumulators. 3-stage cp.async ring, wait 1.
// ---------------------------------------------------------------------------
__global__ void __launch_bounds__(THREADS, 1) gemm_kernel(float* __restrict__ out) {
    extern __shared__ char smem[];
    uint32_t ss = smem_u32(smem);                 // NSTAGE S stages
    uint32_t ws = ss + NSTAGE * SS_STAGE;         // NSTAGE W stages

    int tid = threadIdx.x;
    int w   = tid >> 5;
    int l   = tid & 31;
    int row0 = blockIdx.x * BM;

    unsigned long long acc[RPW][2];
#pragma unroll
    for (int r = 0; r < RPW; r++) { acc[r][0] = 0ULL; acc[r][1] = 0ULL; }

    const char* wbase = (const char*)g_Wt;

    auto issue_stage = [&](int stage, int c) {
        uint32_t sdst = ss + stage * SS_STAGE;
        uint32_t wdst = ws + stage * WS_STAGE;
        const char* wsrc = wbase + (size_t)c * WS_STAGE;
#pragma unroll
        for (int i = 0; i < 3; i++) {
            int t = tid + i * THREADS;
            if (t < BM * 9) {
                int row = t / 9, qq = t - row * 9;
                int grow = row0 + row;
                if (grow >= N_ATOMS) grow = N_ATOMS - 1;   // clamp (discarded later)
                asm volatile("cp.async.ca.shared.global [%0], [%1], 16;"
                             :: "r"(sdst + row * SROW_B + qq * 16),
                                "l"((const char*)(g_S + (size_t)grow * KDIM) +
                                    c * (BK * 4) + qq * 16)
                             : "memory");
            }
        }
#pragma unroll
        for (int i = 0; i < 3; i++) {
            int t = tid + i * THREADS;
            if (t < WS_STAGE / 16) {
                asm volatile("cp.async.ca.shared.global [%0], [%1], 16;"
                             :: "r"(wdst + t * 16), "l"(wsrc + t * 16) : "memory");
            }
        }
        asm volatile("cp.async.commit_group;" ::: "memory");
    };

    // prologue: stages 0 and 1 in flight; require stage 0 before first compute
    issue_stage(0, 0);
    issue_stage(1, 1);
    asm volatile("cp.async.wait_group 1;" ::: "memory");
    __syncthreads();

    int st = 0;
    for (int c = 0; c < NITER; ++c) {
        bool more = (c + 2 < NITER);
        if (more) {
            int nst = st + 2; if (nst >= NSTAGE) nst -= NSTAGE;
            issue_stage(nst, c + 2);          // overwrites stage of c-1 (done at bar)
        }

        uint32_t sa = ss + st * SS_STAGE + (w * RPW) * SROW_B;
        uint32_t wa = ws + st * WS_STAGE + l * 16;

#pragma unroll
        for (int kq = 0; kq < BK / 4; kq++) {
            unsigned long long wv[4][2];
#pragma unroll
            for (int kk = 0; kk < 4; kk++)
                asm("ld.shared.v2.u64 {%0,%1}, [%2];"
                    : "=l"(wv[kk][0]), "=l"(wv[kk][1])
                    : "r"(wa + (kq * 4 + kk) * (NPAD * 4)));

#pragma unroll
            for (int r = 0; r < RPW; r++) {
                float s0, s1, s2, s3;
                asm("ld.shared.v4.f32 {%0,%1,%2,%3}, [%4];"
                    : "=f"(s0), "=f"(s1), "=f"(s2), "=f"(s3)
                    : "r"(sa + r * SROW_B + kq * 16));
                unsigned long long sp[4];
                asm("mov.b64 %0, {%1,%1};" : "=l"(sp[0]) : "f"(s0));
                asm("mov.b64 %0, {%1,%1};" : "=l"(sp[1]) : "f"(s1));
                asm("mov.b64 %0, {%1,%1};" : "=l"(sp[2]) : "f"(s2));
                asm("mov.b64 %0, {%1,%1};" : "=l"(sp[3]) : "f"(s3));
#pragma unroll
                for (int kk = 0; kk < 4; kk++) {
                    asm volatile("fma.rn.f32x2 %0, %1, %2, %0;"
                                 : "+l"(acc[r][0]) : "l"(sp[kk]), "l"(wv[kk][0]));
                    asm volatile("fma.rn.f32x2 %0, %1, %2, %0;"
                                 : "+l"(acc[r][1]) : "l"(sp[kk]), "l"(wv[kk][1]));
                }
            }
        }

        // ensure stage c+1 has landed: with a fresh issue there are 2 groups in
        // flight (c+1, c+2) -> wait 1; at the tail drain fully.
        if (more) asm volatile("cp.async.wait_group 1;" ::: "memory");
        else      asm volatile("cp.async.wait_group 0;" ::: "memory");
        __syncthreads();

        if (++st == NSTAGE) st = 0;
    }

    // epilogue: rows 8w..8w+7 (guard < 16000), cols 4l..4l+3 (guard < 100)
    if (l * 4 < NH) {
#pragma unroll
        for (int r = 0; r < RPW; r++) {
            int row = row0 + w * RPW + r;
            if (row < N_ATOMS) {
                float v0, v1, v2, v3;
                asm("mov.b64 {%0,%1}, %2;" : "=f"(v0), "=f"(v1) : "l"(acc[r][0]));
                asm("mov.b64 {%0,%1}, %2;" : "=f"(v2), "=f"(v3) : "l"(acc[r][1]));
                *(float4*)(out + (size_t)row * NH + l * 4) = make_float4(v0, v1, v2, v3);
            }
        }
    }
}

// ---------------------------------------------------------------------------
extern "C" void kernel_launch(void* const* d_in, const int* in_sizes, int n_in,
                              void* d_out, int out_size) {
    const float* pf  = (const float*)d_in[0];   // [64000, 8]
    const float* af  = (const float*)d_in[1];   // [16000, 100]
    const int*   a2p = (const int*)  d_in[2];   // [64000, 2]
    const float* W   = (const float*)d_in[3];   // [8, 10000]
    const float* b   = (const float*)d_in[4];   // [10000]
    float* out = (float*)d_out;                 // [16000, 100]

    void* cur_ptr = nullptr;
    cudaGetSymbolAddress(&cur_ptr, g_cursor);
    cudaFuncSetAttribute(gemm_kernel,
                         cudaFuncAttributeMaxDynamicSharedMemorySize, SMEM_TOTAL);

    prep_wt_kernel<<<(KDIM * (NPAD / 4) + 255) / 256, 256>>>(W, b);
    cudaMemsetAsync(cur_ptr, 0, N_ATOMS * sizeof(uint32_t));
    fill_kernel<<<(N_PAIRS + 255) / 256, 256>>>(a2p);
    gather_kernel<<<N_ATOMS / 10, 250>>>(pf, af, a2p);
    gemm_kernel<<<GRID, THREADS, SMEM_TOTAL>>>(out);
}